// round 11
// baseline (speedup 1.0000x reference)
#include <cuda_runtime.h>
#include <cuda_bf16.h>
#include <cstdint>

// MeshConv via mma.sync m16n8k16 bf16 split hi/lo (3-term), warp-independent.
// Depth-2 cp.async pipeline: 8 chunks x 4 elements; x rows + neighbor rows all
// gathered as full 128B lines, zero-masked in flight. MMA skeleton unchanged.

#define NK      160
#define TILE_E  128
#define THREADS 128
#define RSTRIDE 336                      // A row stride bytes
#define A_BYTES (TILE_E * RSTRIDE)       // 43008 per split
#define EFOOT   736                      // 4 nbr rows*144 + x row 144 + pad
#define CBUF    (4 * EFOOT)              // 2944 per chunk buffer
#define SM_AHI  0
#define SM_ALO  A_BYTES
#define SM_SCR  (2 * A_BYTES)            // 86016
#define SM_TOTAL (SM_SCR + 4 * 2 * CBUF) // 109568
#define WF_U4   (10 * 8 * 32)

__device__ uint4 g_Wfrag[WF_U4];
__device__ int   g_nbr64;

__device__ __forceinline__ uint32_t pk_bf16x2(float lo, float hi) {
    uint32_t r;
    asm("cvt.rn.satfinite.bf16x2.f32 %0, %1, %2;" : "=r"(r) : "f"(hi), "f"(lo));
    return r;
}

__global__ void meshconv_prep(const float* __restrict__ W,
                              const void* __restrict__ nbr_raw, int E) {
    int i = blockIdx.x * blockDim.x + threadIdx.x;
    if (i < WF_U4) {
        int lane = i & 31;
        int n    = (i >> 5) & 7;
        int ks   = i >> 8;
        int ng = n * 8 + (lane >> 2);
        int k0 = ks * 16 + (lane & 3) * 2;
        float w00 = W[ng * NK + k0],     w01 = W[ng * NK + k0 + 1];
        float w10 = W[ng * NK + k0 + 8], w11 = W[ng * NK + k0 + 9];
        float h00 = __bfloat162float(__float2bfloat16(w00));
        float h01 = __bfloat162float(__float2bfloat16(w01));
        float h10 = __bfloat162float(__float2bfloat16(w10));
        float h11 = __bfloat162float(__float2bfloat16(w11));
        uint4 f;
        f.x = pk_bf16x2(h00, h01);
        f.y = pk_bf16x2(h10, h11);
        f.z = pk_bf16x2(w00 - h00, w01 - h01);
        f.w = pk_bf16x2(w10 - h10, w11 - h11);
        g_Wfrag[i] = f;
    }
    if (i == 0) {
        const long long* p = (const long long*)nbr_raw;
        int ok = 1;
        #pragma unroll
        for (int j = 0; j < 16; j++) {
            long long v = p[j];
            if (v < -(long long)E || v >= (long long)E) ok = 0;
        }
        g_nbr64 = ok;
    }
}

__device__ __forceinline__ uint32_t smem_u32(const void* p) {
    uint32_t a;
    asm("{ .reg .u64 t; cvta.to.shared.u64 t, %1; cvt.u32.u64 %0, t; }" : "=r"(a) : "l"(p));
    return a;
}
__device__ __forceinline__ void ldsm_x4(uint32_t* r, uint32_t addr) {
    asm volatile("ldmatrix.sync.aligned.m8n8.x4.shared.b16 {%0,%1,%2,%3}, [%4];"
                 : "=r"(r[0]), "=r"(r[1]), "=r"(r[2]), "=r"(r[3]) : "r"(addr));
}
__device__ __forceinline__ void mma_bf16(float* d, const uint32_t* a,
                                         uint32_t b0, uint32_t b1) {
    asm volatile(
        "mma.sync.aligned.m16n8k16.row.col.f32.bf16.bf16.f32 "
        "{%0,%1,%2,%3}, {%4,%5,%6,%7}, {%8,%9}, {%0,%1,%2,%3};"
        : "+f"(d[0]), "+f"(d[1]), "+f"(d[2]), "+f"(d[3])
        : "r"(a[0]), "r"(a[1]), "r"(a[2]), "r"(a[3]), "r"(b0), "r"(b1));
}
__device__ __forceinline__ void cp_async16(uint32_t dst, const void* src, int srcsz) {
    asm volatile("cp.async.cg.shared.global [%0], [%1], 16, %2;"
                 :: "r"(dst), "l"(src), "r"(srcsz) : "memory");
}
#define CP_COMMIT() asm volatile("cp.async.commit_group;" ::: "memory")
#define CP_WAIT1()  asm volatile("cp.async.wait_group 1;" ::: "memory")

// 4 floats -> 8B hi bf16x2 + 8B lo bf16x2
__device__ __forceinline__ void split_store(char* hiP, char* loP,
                                            float w0, float w1, float w2, float w3) {
    uint32_t h01 = pk_bf16x2(w0, w1);
    uint32_t h23 = pk_bf16x2(w2, w3);
    float e0 = __uint_as_float(h01 << 16), e1 = __uint_as_float(h01 & 0xFFFF0000u);
    float e2 = __uint_as_float(h23 << 16), e3 = __uint_as_float(h23 & 0xFFFF0000u);
    uint32_t l01 = pk_bf16x2(w0 - e0, w1 - e1);
    uint32_t l23 = pk_bf16x2(w2 - e2, w3 - e3);
    *(uint2*)hiP = make_uint2(h01, h23);
    *(uint2*)loP = make_uint2(l01, l23);
}

__global__ __launch_bounds__(THREADS, 2)
void meshconv_kernel(const float* __restrict__ x,
                     const void* __restrict__ nbr_raw,
                     const float* __restrict__ bias,
                     float* __restrict__ out, int E) {
    extern __shared__ char smem[];
    const uint32_t sbase = smem_u32(smem);
    const int tid  = threadIdx.x;
    const int lane = tid & 31;
    const int warp = tid >> 5;

    const int e0 = blockIdx.x * TILE_E;
    const int j4 = lane >> 3, c8 = lane & 7;     // gather roles
    const int el = lane & 3,  sl = lane >> 2;    // compute roles (4 el x 8 slices)
    const uint32_t scr0 = sbase + SM_SCR + warp * (2 * CBUF);
    char* scrp0 = smem + SM_SCR + warp * (2 * CBUF);
    char* aHiW = smem + SM_AHI;
    char* aLoW = smem + SM_ALO;
    const int nbr64 = g_nbr64;
    const int32_t* nbr32 = (const int32_t*)nbr_raw;
    const long long* nbrLL = (const long long*)nbr_raw;

    // ---- gather one chunk (4 elements) into buffer b ----
    #define ISSUE_CHUNK(ch, b) do {                                            \
        uint32_t dstb = scr0 + (b) * CBUF;                                     \
        _Pragma("unroll")                                                      \
        for (int i = 0; i < 4; i++) {                                          \
            int eg = warp * 32 + (ch) * 4 + i;                                 \
            int er = (e0 + eg) < E ? (e0 + eg) : (E - 1);                      \
            long long nv = nbr64 ? nbrLL[(size_t)er * 4 + j4]                  \
                                 : (long long)nbr32[(size_t)er * 4 + j4];      \
            int idx = (nv < 0) ? -1 : (nv >= E ? E - 1 : (int)nv);             \
            const float* src = x + (size_t)(idx < 0 ? 0 : idx) * 32 + c8 * 4;  \
            cp_async16(dstb + i * EFOOT + j4 * 144 + c8 * 16,                  \
                       src, idx < 0 ? 0 : 16);                                 \
        }                                                                      \
        {   /* x rows of the 4 elements: fully coalesced */                    \
            int eg = warp * 32 + (ch) * 4 + j4;                                \
            int er = (e0 + eg) < E ? (e0 + eg) : (E - 1);                      \
            cp_async16(dstb + j4 * EFOOT + 576 + c8 * 16,                      \
                       x + (size_t)er * 32 + c8 * 4, 16);                      \
        }                                                                      \
    } while (0)

    ISSUE_CHUNK(0, 0); CP_COMMIT();
    ISSUE_CHUNK(1, 1); CP_COMMIT();

    #pragma unroll
    for (int ch = 0; ch < 8; ch++) {
        CP_WAIT1();
        __syncwarp();

        // ---- compute chunk ch from buffer ch&1 ----
        char* bufp = scrp0 + (ch & 1) * CBUF;
        const int egl = warp * 32 + ch * 4 + el;
        char* ebase = bufp + el * EFOOT;

        float4 A0 = *(const float4*)(ebase + 0 * 144 + sl * 16);
        float4 A1 = *(const float4*)(ebase + 1 * 144 + sl * 16);
        float4 B0 = *(const float4*)(ebase + 2 * 144 + sl * 16);
        float4 B1 = *(const float4*)(ebase + 3 * 144 + sl * 16);
        float4 XV = *(const float4*)(ebase + 576      + sl * 16);

        float g1[4], g2[4], g3[4], g4[4];
        {
            float a0[4] = {A0.x, A0.y, A0.z, A0.w};
            float a1[4] = {A1.x, A1.y, A1.z, A1.w};
            float b0[4] = {B0.x, B0.y, B0.z, B0.w};
            float b1[4] = {B1.x, B1.y, B1.z, B1.w};
            #pragma unroll
            for (int j = 0; j < 4; j++) {
                float sa = a0[j] + a1[j], sb = b0[j] + b1[j];
                float da = fabsf(a0[j] - a1[j]), db = fabsf(b0[j] - b1[j]);
                g1[j] = sa + sb;
                g2[j] = da + db;
                g3[j] = fabsf(sa - sb);
                g4[j] = fabsf(da - db);
            }
        }

        char* hrow = aHiW + egl * RSTRIDE + sl * 8;
        char* lrow = aLoW + egl * RSTRIDE + sl * 8;
        split_store(hrow + 0*64, lrow + 0*64, XV.x, XV.y, XV.z, XV.w);
        split_store(hrow + 1*64, lrow + 1*64, g1[0], g1[1], g1[2], g1[3]);
        split_store(hrow + 2*64, lrow + 2*64, g2[0], g2[1], g2[2], g2[3]);
        split_store(hrow + 3*64, lrow + 3*64, g3[0], g3[1], g3[2], g3[3]);
        split_store(hrow + 4*64, lrow + 4*64, g4[0], g4[1], g4[2], g4[3]);

        __syncwarp();                // reads done before buffer reuse
        if (ch + 2 < 8) { ISSUE_CHUNK(ch + 2, ch & 1); }
        CP_COMMIT();                 // keep group count aligned
    }
    #undef ISSUE_CHUNK
    __syncwarp();

    // ---- MMA over own 32 rows ----
    float acc[2][8][4];
    #pragma unroll
    for (int st = 0; st < 2; st++)
        #pragma unroll
        for (int nn = 0; nn < 8; nn++)
            #pragma unroll
            for (int q = 0; q < 4; q++) acc[st][nn][q] = 0.0f;

    const uint32_t arow = (uint32_t)(warp * 32 + (lane & 15));
    const uint32_t aoff = ((uint32_t)(lane >> 4)) * 16;
    const uint32_t ahi0 = sbase + SM_AHI + arow * RSTRIDE + aoff;
    const uint32_t ahi1 = ahi0 + 16 * RSTRIDE;
    const uint32_t alo0 = sbase + SM_ALO + arow * RSTRIDE + aoff;
    const uint32_t alo1 = alo0 + 16 * RSTRIDE;

    #pragma unroll
    for (int ks = 0; ks < 10; ks++) {
        uint32_t fh0[4], fh1[4], fl0[4], fl1[4];
        ldsm_x4(fh0, ahi0 + ks * 32);
        ldsm_x4(fh1, ahi1 + ks * 32);
        ldsm_x4(fl0, alo0 + ks * 32);
        ldsm_x4(fl1, alo1 + ks * 32);
        #pragma unroll
        for (int nn = 0; nn < 8; nn++) {
            uint4 f = __ldg(&g_Wfrag[(ks * 8 + nn) * 32 + lane]);
            mma_bf16(acc[0][nn], fh0, f.x, f.y);
            mma_bf16(acc[0][nn], fh0, f.z, f.w);
            mma_bf16(acc[0][nn], fl0, f.x, f.y);
            mma_bf16(acc[1][nn], fh1, f.x, f.y);
            mma_bf16(acc[1][nn], fh1, f.z, f.w);
            mma_bf16(acc[1][nn], fl1, f.x, f.y);
        }
    }

    // ---- Epilogue ----
    const int colq = (lane & 3) * 2;
    #pragma unroll
    for (int nn = 0; nn < 8; nn++) {
        int col = nn * 8 + colq;
        float2 bv = *(const float2*)(bias + col);
        #pragma unroll
        for (int st = 0; st < 2; st++) {
            int rbase = e0 + warp * 32 + st * 16 + (lane >> 2);
            if (rbase < E) {
                float2 o0 = make_float2(acc[st][nn][0] + bv.x, acc[st][nn][1] + bv.y);
                *(float2*)(out + (size_t)rbase * 64 + col) = o0;
            }
            if (rbase + 8 < E) {
                float2 o1 = make_float2(acc[st][nn][2] + bv.x, acc[st][nn][3] + bv.y);
                *(float2*)(out + (size_t)(rbase + 8) * 64 + col) = o1;
            }
        }
    }
}

extern "C" void kernel_launch(void* const* d_in, const int* in_sizes, int n_in,
                              void* d_out, int out_size) {
    const int E = out_size / 64;
    const float* x = nullptr; const void* nbr = nullptr;
    const float* W = nullptr; const float* b = nullptr;

    for (int i = 0; i < n_in; i++) {
        long long sz = in_sizes[i];
        if (sz == (long long)E * 32)      x   = (const float*)d_in[i];
        else if (sz == (long long)E * 4)  nbr = d_in[i];
        else if (sz == 64 * NK)           W   = (const float*)d_in[i];
        else if (sz == 64)                b   = (const float*)d_in[i];
    }
    float* out = (float*)d_out;

    meshconv_prep<<<(WF_U4 + 255) / 256, 256>>>(W, nbr, E);

    cudaFuncSetAttribute(meshconv_kernel,
                         cudaFuncAttributeMaxDynamicSharedMemorySize, SM_TOTAL);
    int nb = (E + TILE_E - 1) / TILE_E;
    meshconv_kernel<<<nb, THREADS, SM_TOTAL>>>(x, nbr, b, out, E);
}

// round 12
// speedup vs baseline: 1.1390x; 1.1390x over previous
#include <cuda_runtime.h>
#include <cuda_bf16.h>
#include <cstdint>

// MeshConv via mma.sync m16n8k16 bf16 split hi/lo (3-term), warp-independent.
// R10 skeleton + depth-2 cp.async pipeline at chunk=8, second buffer aliased
// into the warp's own A rows 24-31 (written only by the final chunk).

#define NK      160
#define TILE_E  128
#define THREADS 128
#define RSTRIDE 336                      // A row stride bytes
#define A_BYTES (TILE_E * RSTRIDE)       // 43008 per split
#define EFOOT   592                      // scratch bytes per element
#define SCR_W   (8 * EFOOT)              // 4736 per warp (bufX)
#define SM_AHI  0
#define SM_ALO  A_BYTES
#define SM_SCR  (2 * A_BYTES)            // 86016
#define SM_IDX  (SM_SCR + 4 * SCR_W)     // 104960
#define SM_TOTAL (SM_IDX + TILE_E * 4 * 4)   // 107008 (== R10)
#define WF_U4   (10 * 8 * 32)

__device__ uint4 g_Wfrag[WF_U4];
__device__ int   g_nbr64;

__device__ __forceinline__ uint32_t pk_bf16x2(float lo, float hi) {
    uint32_t r;
    asm("cvt.rn.satfinite.bf16x2.f32 %0, %1, %2;" : "=r"(r) : "f"(hi), "f"(lo));
    return r;
}

__global__ void meshconv_prep(const float* __restrict__ W,
                              const void* __restrict__ nbr_raw, int E) {
    int i = blockIdx.x * blockDim.x + threadIdx.x;
    if (i < WF_U4) {
        int lane = i & 31;
        int n    = (i >> 5) & 7;
        int ks   = i >> 8;
        int ng = n * 8 + (lane >> 2);
        int k0 = ks * 16 + (lane & 3) * 2;
        float w00 = W[ng * NK + k0],     w01 = W[ng * NK + k0 + 1];
        float w10 = W[ng * NK + k0 + 8], w11 = W[ng * NK + k0 + 9];
        float h00 = __bfloat162float(__float2bfloat16(w00));
        float h01 = __bfloat162float(__float2bfloat16(w01));
        float h10 = __bfloat162float(__float2bfloat16(w10));
        float h11 = __bfloat162float(__float2bfloat16(w11));
        uint4 f;
        f.x = pk_bf16x2(h00, h01);
        f.y = pk_bf16x2(h10, h11);
        f.z = pk_bf16x2(w00 - h00, w01 - h01);
        f.w = pk_bf16x2(w10 - h10, w11 - h11);
        g_Wfrag[i] = f;
    }
    if (i == 0) {
        const long long* p = (const long long*)nbr_raw;
        int ok = 1;
        #pragma unroll
        for (int j = 0; j < 16; j++) {
            long long v = p[j];
            if (v < -(long long)E || v >= (long long)E) ok = 0;
        }
        g_nbr64 = ok;
    }
}

__device__ __forceinline__ uint32_t smem_u32(const void* p) {
    uint32_t a;
    asm("{ .reg .u64 t; cvta.to.shared.u64 t, %1; cvt.u32.u64 %0, t; }" : "=r"(a) : "l"(p));
    return a;
}
__device__ __forceinline__ void ldsm_x4(uint32_t* r, uint32_t addr) {
    asm volatile("ldmatrix.sync.aligned.m8n8.x4.shared.b16 {%0,%1,%2,%3}, [%4];"
                 : "=r"(r[0]), "=r"(r[1]), "=r"(r[2]), "=r"(r[3]) : "r"(addr));
}
__device__ __forceinline__ void mma_bf16(float* d, const uint32_t* a,
                                         uint32_t b0, uint32_t b1) {
    asm volatile(
        "mma.sync.aligned.m16n8k16.row.col.f32.bf16.bf16.f32 "
        "{%0,%1,%2,%3}, {%4,%5,%6,%7}, {%8,%9}, {%0,%1,%2,%3};"
        : "+f"(d[0]), "+f"(d[1]), "+f"(d[2]), "+f"(d[3])
        : "r"(a[0]), "r"(a[1]), "r"(a[2]), "r"(a[3]), "r"(b0), "r"(b1));
}
__device__ __forceinline__ void cp_async16(uint32_t dst, const void* src, int srcsz) {
    asm volatile("cp.async.cg.shared.global [%0], [%1], 16, %2;"
                 :: "r"(dst), "l"(src), "r"(srcsz) : "memory");
}
#define CP_COMMIT() asm volatile("cp.async.commit_group;" ::: "memory")
#define CP_WAIT(n)  asm volatile("cp.async.wait_group %0;" :: "n"(n) : "memory")

// 4 floats -> 8B hi bf16x2 + 8B lo bf16x2
__device__ __forceinline__ void split_store(char* hiP, char* loP,
                                            float w0, float w1, float w2, float w3) {
    uint32_t h01 = pk_bf16x2(w0, w1);
    uint32_t h23 = pk_bf16x2(w2, w3);
    float e0 = __uint_as_float(h01 << 16), e1 = __uint_as_float(h01 & 0xFFFF0000u);
    float e2 = __uint_as_float(h23 << 16), e3 = __uint_as_float(h23 & 0xFFFF0000u);
    uint32_t l01 = pk_bf16x2(w0 - e0, w1 - e1);
    uint32_t l23 = pk_bf16x2(w2 - e2, w3 - e3);
    *(uint2*)hiP = make_uint2(h01, h23);
    *(uint2*)loP = make_uint2(l01, l23);
}

__global__ __launch_bounds__(THREADS, 2)
void meshconv_kernel(const float* __restrict__ x,
                     const void* __restrict__ nbr_raw,
                     const float* __restrict__ bias,
                     float* __restrict__ out, int E) {
    extern __shared__ char smem[];
    const uint32_t sbase = smem_u32(smem);
    const int tid  = threadIdx.x;
    const int lane = tid & 31;
    const int warp = tid >> 5;
    int* sIdx = (int*)(smem + SM_IDX);

    const int e0 = blockIdx.x * TILE_E;

    // ---- resolve neighbor indices once ----
    {
        const int er = (e0 + tid) < E ? (e0 + tid) : (E - 1);
        long long n[4];
        if (g_nbr64) {
            const long long* nb = (const long long*)nbr_raw + (size_t)er * 4;
            n[0] = nb[0]; n[1] = nb[1]; n[2] = nb[2]; n[3] = nb[3];
        } else {
            const int* nb = (const int*)nbr_raw + (size_t)er * 4;
            n[0] = nb[0]; n[1] = nb[1]; n[2] = nb[2]; n[3] = nb[3];
        }
        int4 w;
        w.x = (n[0] < 0) ? -1 : (n[0] >= E ? E - 1 : (int)n[0]);
        w.y = (n[1] < 0) ? -1 : (n[1] >= E ? E - 1 : (int)n[1]);
        w.z = (n[2] < 0) ? -1 : (n[2] >= E ? E - 1 : (int)n[2]);
        w.w = (n[3] < 0) ? -1 : (n[3] >= E ? E - 1 : (int)n[3]);
        *(int4*)(sIdx + tid * 4) = w;
    }
    __syncwarp();

    const int j8 = lane >> 3, c8 = lane & 7;     // gather roles
    const int el = lane & 7,  sl = lane >> 3;    // compute roles
    char* aHiW = smem + SM_AHI;
    char* aLoW = smem + SM_ALO;

    // buffers: bufX = dedicated scratch; bufZ = aliased into A rows 24-31 of
    // this warp (hi zone: el 0-3, lo zone: el 4-7). Those rows are written
    // only by chunk 3's compute.
    const uint32_t bufX   = sbase + SM_SCR + warp * SCR_W;
    const uint32_t zoneHi = sbase + SM_AHI + (uint32_t)(warp * 32 + 24) * RSTRIDE;
    const uint32_t zoneLo = sbase + SM_ALO + (uint32_t)(warp * 32 + 24) * RSTRIDE;
    char* bufXp   = smem + SM_SCR + warp * SCR_W;
    char* zoneHip = smem + SM_AHI + (size_t)(warp * 32 + 24) * RSTRIDE;
    char* zoneLop = smem + SM_ALO + (size_t)(warp * 32 + 24) * RSTRIDE;

    #define SLOT_U32(sel, i) ((sel) == 0 ? bufX + (i) * EFOOT                         \
                              : ((i) < 4 ? zoneHi + (i) * EFOOT                       \
                                         : zoneLo + ((i) - 4) * EFOOT))
    #define SLOT_PTR(sel, i) ((sel) == 0 ? bufXp + (i) * EFOOT                        \
                              : ((i) < 4 ? zoneHip + (i) * EFOOT                      \
                                         : zoneLop + ((i) - 4) * EFOOT))

    #define ISSUE_CHUNK(ch, sel) do {                                                 \
        _Pragma("unroll")                                                             \
        for (int i = 0; i < 8; i++) {                                                 \
            int eg  = warp * 32 + (ch) * 8 + i;                                       \
            int idx = sIdx[eg * 4 + j8];                                              \
            const float* src = x + (size_t)(idx < 0 ? 0 : idx) * 32 + c8 * 4;         \
            cp_async16(SLOT_U32(sel, i) + j8 * 144 + c8 * 16,                         \
                       src, idx < 0 ? 0 : 16);                                        \
        }                                                                             \
        CP_COMMIT();                                                                  \
    } while (0)

    #define COMPUTE_CHUNK(ch, sel) do {                                               \
        const int egl = warp * 32 + (ch) * 8 + el;                                    \
        const int erg = (e0 + egl) < E ? (e0 + egl) : (E - 1);                        \
        char* ebase = SLOT_PTR(sel, el);                                              \
        float4 a0l = *(const float4*)(ebase + 0 * 144 + sl * 32);                     \
        float4 a0h = *(const float4*)(ebase + 0 * 144 + sl * 32 + 16);                \
        float4 a1l = *(const float4*)(ebase + 1 * 144 + sl * 32);                     \
        float4 a1h = *(const float4*)(ebase + 1 * 144 + sl * 32 + 16);                \
        float4 b0l = *(const float4*)(ebase + 2 * 144 + sl * 32);                     \
        float4 b0h = *(const float4*)(ebase + 2 * 144 + sl * 32 + 16);                \
        float4 b1l = *(const float4*)(ebase + 3 * 144 + sl * 32);                     \
        float4 b1h = *(const float4*)(ebase + 3 * 144 + sl * 32 + 16);                \
        float4 xv0 = __ldg((const float4*)(x + (size_t)erg * 32 + sl * 8));           \
        float4 xv1 = __ldg((const float4*)(x + (size_t)erg * 32 + sl * 8 + 4));       \
        __syncwarp();   /* all reads done before any writes (zone aliasing) */        \
        float A0[8] = {a0l.x,a0l.y,a0l.z,a0l.w,a0h.x,a0h.y,a0h.z,a0h.w};              \
        float A1[8] = {a1l.x,a1l.y,a1l.z,a1l.w,a1h.x,a1h.y,a1h.z,a1h.w};              \
        float B0[8] = {b0l.x,b0l.y,b0l.z,b0l.w,b0h.x,b0h.y,b0h.z,b0h.w};              \
        float B1[8] = {b1l.x,b1l.y,b1l.z,b1l.w,b1h.x,b1h.y,b1h.z,b1h.w};              \
        float XV[8] = {xv0.x,xv0.y,xv0.z,xv0.w,xv1.x,xv1.y,xv1.z,xv1.w};              \
        float g1[8], g2[8], g3[8], g4[8];                                             \
        _Pragma("unroll")                                                             \
        for (int j = 0; j < 8; j++) {                                                 \
            float sa = A0[j] + A1[j], sb = B0[j] + B1[j];                             \
            float da = fabsf(A0[j] - A1[j]), db = fabsf(B0[j] - B1[j]);               \
            g1[j] = sa + sb;                                                          \
            g2[j] = da + db;                                                          \
            g3[j] = fabsf(sa - sb);                                                   \
            g4[j] = fabsf(da - db);                                                   \
        }                                                                             \
        char* hrow = aHiW + egl * RSTRIDE + sl * 16;                                  \
        char* lrow = aLoW + egl * RSTRIDE + sl * 16;                                  \
        split_store(hrow + 0*64 + 0, lrow + 0*64 + 0, XV[0], XV[1], XV[2], XV[3]);    \
        split_store(hrow + 0*64 + 8, lrow + 0*64 + 8, XV[4], XV[5], XV[6], XV[7]);    \
        split_store(hrow + 1*64 + 0, lrow + 1*64 + 0, g1[0], g1[1], g1[2], g1[3]);    \
        split_store(hrow + 1*64 + 8, lrow + 1*64 + 8, g1[4], g1[5], g1[6], g1[7]);    \
        split_store(hrow + 2*64 + 0, lrow + 2*64 + 0, g2[0], g2[1], g2[2], g2[3]);    \
        split_store(hrow + 2*64 + 8, lrow + 2*64 + 8, g2[4], g2[5], g2[6], g2[7]);    \
        split_store(hrow + 3*64 + 0, lrow + 3*64 + 0, g3[0], g3[1], g3[2], g3[3]);    \
        split_store(hrow + 3*64 + 8, lrow + 3*64 + 8, g3[4], g3[5], g3[6], g3[7]);    \
        split_store(hrow + 4*64 + 0, lrow + 4*64 + 0, g4[0], g4[1], g4[2], g4[3]);    \
        split_store(hrow + 4*64 + 8, lrow + 4*64 + 8, g4[4], g4[5], g4[6], g4[7]);    \
    } while (0)

    // depth-2 pipeline over 4 chunks
    ISSUE_CHUNK(0, 0);
    ISSUE_CHUNK(1, 1);
    CP_WAIT(1); __syncwarp();
    COMPUTE_CHUNK(0, 0);          // writes rows 0-7
    __syncwarp();
    ISSUE_CHUNK(2, 0);
    CP_WAIT(1); __syncwarp();
    COMPUTE_CHUNK(1, 1);          // writes rows 8-15
    __syncwarp();
    ISSUE_CHUNK(3, 1);
    CP_WAIT(1); __syncwarp();
    COMPUTE_CHUNK(2, 0);          // writes rows 16-23
    CP_WAIT(0); __syncwarp();
    COMPUTE_CHUNK(3, 1);          // reads zone, then overwrites rows 24-31
    __syncwarp();

    #undef ISSUE_CHUNK
    #undef COMPUTE_CHUNK
    #undef SLOT_U32
    #undef SLOT_PTR

    // ---- MMA over own 32 rows ----
    float acc[2][8][4];
    #pragma unroll
    for (int st = 0; st < 2; st++)
        #pragma unroll
        for (int nn = 0; nn < 8; nn++)
            #pragma unroll
            for (int q = 0; q < 4; q++) acc[st][nn][q] = 0.0f;

    const uint32_t arow = (uint32_t)(warp * 32 + (lane & 15));
    const uint32_t aoff = ((uint32_t)(lane >> 4)) * 16;
    const uint32_t ahi0 = sbase + SM_AHI + arow * RSTRIDE + aoff;
    const uint32_t ahi1 = ahi0 + 16 * RSTRIDE;
    const uint32_t alo0 = sbase + SM_ALO + arow * RSTRIDE + aoff;
    const uint32_t alo1 = alo0 + 16 * RSTRIDE;

    #pragma unroll
    for (int ks = 0; ks < 10; ks++) {
        uint32_t fh0[4], fh1[4], fl0[4], fl1[4];
        ldsm_x4(fh0, ahi0 + ks * 32);
        ldsm_x4(fh1, ahi1 + ks * 32);
        ldsm_x4(fl0, alo0 + ks * 32);
        ldsm_x4(fl1, alo1 + ks * 32);
        #pragma unroll
        for (int nn = 0; nn < 8; nn++) {
            uint4 f = __ldg(&g_Wfrag[(ks * 8 + nn) * 32 + lane]);
            mma_bf16(acc[0][nn], fh0, f.x, f.y);
            mma_bf16(acc[0][nn], fh0, f.z, f.w);
            mma_bf16(acc[0][nn], fl0, f.x, f.y);
            mma_bf16(acc[1][nn], fh1, f.x, f.y);
            mma_bf16(acc[1][nn], fh1, f.z, f.w);
            mma_bf16(acc[1][nn], fl1, f.x, f.y);
        }
    }

    // ---- Epilogue ----
    const int colq = (lane & 3) * 2;
    #pragma unroll
    for (int nn = 0; nn < 8; nn++) {
        int col = nn * 8 + colq;
        float2 bv = *(const float2*)(bias + col);
        #pragma unroll
        for (int st = 0; st < 2; st++) {
            int rbase = e0 + warp * 32 + st * 16 + (lane >> 2);
            if (rbase < E) {
                float2 o0 = make_float2(acc[st][nn][0] + bv.x, acc[st][nn][1] + bv.y);
                *(float2*)(out + (size_t)rbase * 64 + col) = o0;
            }
            if (rbase + 8 < E) {
                float2 o1 = make_float2(acc[st][nn][2] + bv.x, acc[st][nn][3] + bv.y);
                *(float2*)(out + (size_t)(rbase + 8) * 64 + col) = o1;
            }
        }
    }
}

extern "C" void kernel_launch(void* const* d_in, const int* in_sizes, int n_in,
                              void* d_out, int out_size) {
    const int E = out_size / 64;
    const float* x = nullptr; const void* nbr = nullptr;
    const float* W = nullptr; const float* b = nullptr;

    for (int i = 0; i < n_in; i++) {
        long long sz = in_sizes[i];
        if (sz == (long long)E * 32)      x   = (const float*)d_in[i];
        else if (sz == (long long)E * 4)  nbr = d_in[i];
        else if (sz == 64 * NK)           W   = (const float*)d_in[i];
        else if (sz == 64)                b   = (const float*)d_in[i];
    }
    float* out = (float*)d_out;

    meshconv_prep<<<(WF_U4 + 255) / 256, 256>>>(W, nbr, E);

    cudaFuncSetAttribute(meshconv_kernel,
                         cudaFuncAttributeMaxDynamicSharedMemorySize, SM_TOTAL);
    int nb = (E + TILE_E - 1) / TILE_E;
    meshconv_kernel<<<nb, THREADS, SM_TOTAL>>>(x, nbr, b, out, E);
}

// round 13
// speedup vs baseline: 1.4557x; 1.2780x over previous
#include <cuda_runtime.h>
#include <cuda_fp16.h>
#include <cstdint>

// MeshConv via mma.sync m16n8k16 fp16, 2-term split:
//   out = A_fp16 @ (Whi + Wlo) ,  A rounded once to fp16 (err ~2^-12, ~1e-4 final)
// Warp-independent tiles, cp.async full-line gather (R10 flow), 3 CTAs/SM.

#define NK      160
#define TILE_E  128
#define THREADS 128
#define RSTRIDE 336                      // A row stride bytes (336 mod 128 = 80 -> cf)
#define A_BYTES (TILE_E * RSTRIDE)       // 43008
#define EFOOT   592                      // scratch bytes per element
#define SCR_W   (8 * EFOOT)              // 4736 per warp
#define SM_A    0
#define SM_SCR  A_BYTES                  // 43008
#define SM_IDX  (SM_SCR + 4 * SCR_W)     // 61952
#define SM_TOTAL (SM_IDX + TILE_E * 4 * 4)   // 64000
#define WF_U4   (10 * 8 * 32)

__device__ uint4 g_Wfrag[WF_U4];         // {bhi0, bhi1, blo0, blo1} fp16x2 each
__device__ int   g_nbr64;

__device__ __forceinline__ uint32_t pk_f16x2(float lo, float hi) {
    uint32_t r;
    asm("cvt.rn.f16x2.f32 %0, %1, %2;" : "=r"(r) : "f"(hi), "f"(lo));
    return r;   // low half = lo, high half = hi
}

__global__ void meshconv_prep(const float* __restrict__ W,
                              const void* __restrict__ nbr_raw, int E) {
    int i = blockIdx.x * blockDim.x + threadIdx.x;
    if (i < WF_U4) {
        // m16n8k16 B-fragment: lane l -> b0:k=(l%4)*2(+1),n=l/4 ; b1: k+8
        int lane = i & 31;
        int n    = (i >> 5) & 7;
        int ks   = i >> 8;
        int ng = n * 8 + (lane >> 2);
        int k0 = ks * 16 + (lane & 3) * 2;
        float w00 = W[ng * NK + k0],     w01 = W[ng * NK + k0 + 1];
        float w10 = W[ng * NK + k0 + 8], w11 = W[ng * NK + k0 + 9];
        float h00 = __half2float(__float2half_rn(w00));
        float h01 = __half2float(__float2half_rn(w01));
        float h10 = __half2float(__float2half_rn(w10));
        float h11 = __half2float(__float2half_rn(w11));
        uint4 f;
        f.x = pk_f16x2(h00, h01);               // W_hi reg0
        f.y = pk_f16x2(h10, h11);               // W_hi reg1
        f.z = pk_f16x2(w00 - h00, w01 - h01);   // W_lo reg0
        f.w = pk_f16x2(w10 - h10, w11 - h11);   // W_lo reg1
        g_Wfrag[i] = f;
    }
    if (i == 0) {
        const long long* p = (const long long*)nbr_raw;
        int ok = 1;
        #pragma unroll
        for (int j = 0; j < 16; j++) {
            long long v = p[j];
            if (v < -(long long)E || v >= (long long)E) ok = 0;
        }
        g_nbr64 = ok;
    }
}

__device__ __forceinline__ uint32_t smem_u32(const void* p) {
    uint32_t a;
    asm("{ .reg .u64 t; cvta.to.shared.u64 t, %1; cvt.u32.u64 %0, t; }" : "=r"(a) : "l"(p));
    return a;
}
__device__ __forceinline__ void ldsm_x4(uint32_t* r, uint32_t addr) {
    asm volatile("ldmatrix.sync.aligned.m8n8.x4.shared.b16 {%0,%1,%2,%3}, [%4];"
                 : "=r"(r[0]), "=r"(r[1]), "=r"(r[2]), "=r"(r[3]) : "r"(addr));
}
__device__ __forceinline__ void mma_f16(float* d, const uint32_t* a,
                                        uint32_t b0, uint32_t b1) {
    asm volatile(
        "mma.sync.aligned.m16n8k16.row.col.f32.f16.f16.f32 "
        "{%0,%1,%2,%3}, {%4,%5,%6,%7}, {%8,%9}, {%0,%1,%2,%3};"
        : "+f"(d[0]), "+f"(d[1]), "+f"(d[2]), "+f"(d[3])
        : "r"(a[0]), "r"(a[1]), "r"(a[2]), "r"(a[3]), "r"(b0), "r"(b1));
}
__device__ __forceinline__ void cp_async16(uint32_t dst, const void* src, int srcsz) {
    asm volatile("cp.async.cg.shared.global [%0], [%1], 16, %2;"
                 :: "r"(dst), "l"(src), "r"(srcsz) : "memory");
}

// 8 floats -> one 16B fp16 STS.128
__device__ __forceinline__ void st_f16x8(char* p, const float* v) {
    uint4 u;
    u.x = pk_f16x2(v[0], v[1]);
    u.y = pk_f16x2(v[2], v[3]);
    u.z = pk_f16x2(v[4], v[5]);
    u.w = pk_f16x2(v[6], v[7]);
    *(uint4*)p = u;
}

__global__ __launch_bounds__(THREADS, 3)
void meshconv_kernel(const float* __restrict__ x,
                     const void* __restrict__ nbr_raw,
                     const float* __restrict__ bias,
                     float* __restrict__ out, int E) {
    extern __shared__ char smem[];
    const uint32_t sbase = smem_u32(smem);
    const int tid  = threadIdx.x;
    const int lane = tid & 31;
    const int warp = tid >> 5;
    int* sIdx = (int*)(smem + SM_IDX);

    const int e0 = blockIdx.x * TILE_E;

    // ---- resolve neighbor indices once ----
    {
        const int er = (e0 + tid) < E ? (e0 + tid) : (E - 1);
        long long n[4];
        if (g_nbr64) {
            const long long* nb = (const long long*)nbr_raw + (size_t)er * 4;
            n[0] = nb[0]; n[1] = nb[1]; n[2] = nb[2]; n[3] = nb[3];
        } else {
            const int* nb = (const int*)nbr_raw + (size_t)er * 4;
            n[0] = nb[0]; n[1] = nb[1]; n[2] = nb[2]; n[3] = nb[3];
        }
        int4 w;
        w.x = (n[0] < 0) ? -1 : (n[0] >= E ? E - 1 : (int)n[0]);
        w.y = (n[1] < 0) ? -1 : (n[1] >= E ? E - 1 : (int)n[1]);
        w.z = (n[2] < 0) ? -1 : (n[2] >= E ? E - 1 : (int)n[2]);
        w.w = (n[3] < 0) ? -1 : (n[3] >= E ? E - 1 : (int)n[3]);
        *(int4*)(sIdx + tid * 4) = w;
    }
    __syncwarp();

    const int j8 = lane >> 3, c8 = lane & 7;     // gather roles
    const int el = lane & 7,  sl = lane >> 3;    // compute roles (8 el x 4 slices)
    const uint32_t scr = sbase + SM_SCR + warp * SCR_W;
    char* scrp = smem + SM_SCR + warp * SCR_W;
    char* aW   = smem + SM_A;

    #pragma unroll
    for (int ch = 0; ch < 4; ch++) {
        // ---- cooperative full-line gather: 8 elements x 4 neighbor rows ----
        #pragma unroll
        for (int i = 0; i < 8; i++) {
            int eg  = warp * 32 + ch * 8 + i;
            int idx = sIdx[eg * 4 + j8];
            const float* src = x + (size_t)(idx < 0 ? 0 : idx) * 32 + c8 * 4;
            cp_async16(scr + i * EFOOT + j8 * 144 + c8 * 16, src, idx < 0 ? 0 : 16);
        }
        asm volatile("cp.async.commit_group;" ::: "memory");
        asm volatile("cp.async.wait_group 0;" ::: "memory");
        __syncwarp();

        // ---- local feature build: lane owns (element el, 8-channel slice sl) ----
        const int egl = warp * 32 + ch * 8 + el;
        const int erg = (e0 + egl) < E ? (e0 + egl) : (E - 1);

        float4 a0l = *(const float4*)(scrp + el * EFOOT + 0 * 144 + sl * 32);
        float4 a0h = *(const float4*)(scrp + el * EFOOT + 0 * 144 + sl * 32 + 16);
        float4 a1l = *(const float4*)(scrp + el * EFOOT + 1 * 144 + sl * 32);
        float4 a1h = *(const float4*)(scrp + el * EFOOT + 1 * 144 + sl * 32 + 16);
        float4 b0l = *(const float4*)(scrp + el * EFOOT + 2 * 144 + sl * 32);
        float4 b0h = *(const float4*)(scrp + el * EFOOT + 2 * 144 + sl * 32 + 16);
        float4 b1l = *(const float4*)(scrp + el * EFOOT + 3 * 144 + sl * 32);
        float4 b1h = *(const float4*)(scrp + el * EFOOT + 3 * 144 + sl * 32 + 16);
        float4 xv0 = __ldg((const float4*)(x + (size_t)erg * 32 + sl * 8));
        float4 xv1 = __ldg((const float4*)(x + (size_t)erg * 32 + sl * 8 + 4));

        float A0[8] = {a0l.x,a0l.y,a0l.z,a0l.w,a0h.x,a0h.y,a0h.z,a0h.w};
        float A1[8] = {a1l.x,a1l.y,a1l.z,a1l.w,a1h.x,a1h.y,a1h.z,a1h.w};
        float B0[8] = {b0l.x,b0l.y,b0l.z,b0l.w,b0h.x,b0h.y,b0h.z,b0h.w};
        float B1[8] = {b1l.x,b1l.y,b1l.z,b1l.w,b1h.x,b1h.y,b1h.z,b1h.w};
        float XV[8] = {xv0.x,xv0.y,xv0.z,xv0.w,xv1.x,xv1.y,xv1.z,xv1.w};

        float g1[8], g2[8], g3[8], g4[8];
        #pragma unroll
        for (int j = 0; j < 8; j++) {
            float sa = A0[j] + A1[j], sb = B0[j] + B1[j];
            float da = fabsf(A0[j] - A1[j]), db = fabsf(B0[j] - B1[j]);
            g1[j] = sa + sb;
            g2[j] = da + db;
            g3[j] = fabsf(sa - sb);
            g4[j] = fabsf(da - db);
        }

        // slice sl of group g at byte offset g*64 + sl*16 (one STS.128 each)
        char* arow = aW + egl * RSTRIDE + sl * 16;
        st_f16x8(arow + 0 * 64, XV);
        st_f16x8(arow + 1 * 64, g1);
        st_f16x8(arow + 2 * 64, g2);
        st_f16x8(arow + 3 * 64, g3);
        st_f16x8(arow + 4 * 64, g4);
        __syncwarp();   // scratch reuse next chunk
    }
    __syncwarp();

    // ---- MMA over own 32 rows: 2 terms (Whi, Wlo) ----
    float acc[2][8][4];
    #pragma unroll
    for (int st = 0; st < 2; st++)
        #pragma unroll
        for (int nn = 0; nn < 8; nn++)
            #pragma unroll
            for (int q = 0; q < 4; q++) acc[st][nn][q] = 0.0f;

    const uint32_t arow = (uint32_t)(warp * 32 + (lane & 15));
    const uint32_t aoff = ((uint32_t)(lane >> 4)) * 16;
    const uint32_t a0 = sbase + SM_A + arow * RSTRIDE + aoff;
    const uint32_t a1 = a0 + 16 * RSTRIDE;

    #pragma unroll
    for (int ks = 0; ks < 10; ks++) {
        uint32_t f0[4], f1[4];
        ldsm_x4(f0, a0 + ks * 32);
        ldsm_x4(f1, a1 + ks * 32);
        #pragma unroll
        for (int nn = 0; nn < 8; nn++) {
            uint4 f = __ldg(&g_Wfrag[(ks * 8 + nn) * 32 + lane]);
            mma_f16(acc[0][nn], f0, f.x, f.y);   // A * Whi
            mma_f16(acc[0][nn], f0, f.z, f.w);   // A * Wlo
            mma_f16(acc[1][nn], f1, f.x, f.y);
            mma_f16(acc[1][nn], f1, f.z, f.w);
        }
    }

    // ---- Epilogue ----
    const int colq = (lane & 3) * 2;
    #pragma unroll
    for (int nn = 0; nn < 8; nn++) {
        int col = nn * 8 + colq;
        float2 bv = *(const float2*)(bias + col);
        #pragma unroll
        for (int st = 0; st < 2; st++) {
            int rbase = e0 + warp * 32 + st * 16 + (lane >> 2);
            if (rbase < E) {
                float2 o0 = make_float2(acc[st][nn][0] + bv.x, acc[st][nn][1] + bv.y);
                *(float2*)(out + (size_t)rbase * 64 + col) = o0;
            }
            if (rbase + 8 < E) {
                float2 o1 = make_float2(acc[st][nn][2] + bv.x, acc[st][nn][3] + bv.y);
                *(float2*)(out + (size_t)(rbase + 8) * 64 + col) = o1;
            }
        }
    }
}

extern "C" void kernel_launch(void* const* d_in, const int* in_sizes, int n_in,
                              void* d_out, int out_size) {
    const int E = out_size / 64;
    const float* x = nullptr; const void* nbr = nullptr;
    const float* W = nullptr; const float* b = nullptr;

    for (int i = 0; i < n_in; i++) {
        long long sz = in_sizes[i];
        if (sz == (long long)E * 32)      x   = (const float*)d_in[i];
        else if (sz == (long long)E * 4)  nbr = d_in[i];
        else if (sz == 64 * NK)           W   = (const float*)d_in[i];
        else if (sz == 64)                b   = (const float*)d_in[i];
    }
    float* out = (float*)d_out;

    meshconv_prep<<<(WF_U4 + 255) / 256, 256>>>(W, nbr, E);

    cudaFuncSetAttribute(meshconv_kernel,
                         cudaFuncAttributeMaxDynamicSharedMemorySize, SM_TOTAL);
    int nb = (E + TILE_E - 1) / TILE_E;
    meshconv_kernel<<<nb, THREADS, SM_TOTAL>>>(x, nbr, b, out, E);
}

// round 14
// speedup vs baseline: 1.5994x; 1.0987x over previous
#include <cuda_runtime.h>
#include <cuda_fp16.h>
#include <cstdint>

// MeshConv via mma.sync m16n8k16 fp16, single term: out ~= A_fp16 @ W_fp16 + b.
// Error ~3e-4 (A and W each rounded once to fp16; K=160 accumulation in fp32).
// Warp-independent tiles, cp.async full-line gather, 3 CTAs/SM.

#define NK      160
#define TILE_E  128
#define THREADS 128
#define RSTRIDE 336                      // A row stride bytes
#define A_BYTES (TILE_E * RSTRIDE)       // 43008
#define EFOOT   592                      // scratch bytes per element
#define SCR_W   (8 * EFOOT)              // 4736 per warp
#define SM_A    0
#define SM_SCR  A_BYTES                  // 43008
#define SM_IDX  (SM_SCR + 4 * SCR_W)     // 61952
#define SM_TOTAL (SM_IDX + TILE_E * 4 * 4)   // 64000
#define WF_N    (10 * 8 * 32)

__device__ uint2 g_Wfrag[WF_N];          // {b0, b1} fp16x2 (hi only)
__device__ int   g_nbr64;

__device__ __forceinline__ uint32_t pk_f16x2(float lo, float hi) {
    uint32_t r;
    asm("cvt.rn.f16x2.f32 %0, %1, %2;" : "=r"(r) : "f"(hi), "f"(lo));
    return r;
}

__global__ void meshconv_prep(const float* __restrict__ W,
                              const void* __restrict__ nbr_raw, int E) {
    int i = blockIdx.x * blockDim.x + threadIdx.x;
    if (i < WF_N) {
        // m16n8k16 B-fragment: lane l -> b0:k=(l%4)*2(+1),n=l/4 ; b1: k+8
        int lane = i & 31;
        int n    = (i >> 5) & 7;
        int ks   = i >> 8;
        int ng = n * 8 + (lane >> 2);
        int k0 = ks * 16 + (lane & 3) * 2;
        uint2 f;
        f.x = pk_f16x2(W[ng * NK + k0],     W[ng * NK + k0 + 1]);
        f.y = pk_f16x2(W[ng * NK + k0 + 8], W[ng * NK + k0 + 9]);
        g_Wfrag[i] = f;
    }
    if (i == 0) {
        const long long* p = (const long long*)nbr_raw;
        int ok = 1;
        #pragma unroll
        for (int j = 0; j < 16; j++) {
            long long v = p[j];
            if (v < -(long long)E || v >= (long long)E) ok = 0;
        }
        g_nbr64 = ok;
    }
}

__device__ __forceinline__ uint32_t smem_u32(const void* p) {
    uint32_t a;
    asm("{ .reg .u64 t; cvta.to.shared.u64 t, %1; cvt.u32.u64 %0, t; }" : "=r"(a) : "l"(p));
    return a;
}
__device__ __forceinline__ void ldsm_x4(uint32_t* r, uint32_t addr) {
    asm volatile("ldmatrix.sync.aligned.m8n8.x4.shared.b16 {%0,%1,%2,%3}, [%4];"
                 : "=r"(r[0]), "=r"(r[1]), "=r"(r[2]), "=r"(r[3]) : "r"(addr));
}
__device__ __forceinline__ void mma_f16(float* d, const uint32_t* a,
                                        uint32_t b0, uint32_t b1) {
    asm volatile(
        "mma.sync.aligned.m16n8k16.row.col.f32.f16.f16.f32 "
        "{%0,%1,%2,%3}, {%4,%5,%6,%7}, {%8,%9}, {%0,%1,%2,%3};"
        : "+f"(d[0]), "+f"(d[1]), "+f"(d[2]), "+f"(d[3])
        : "r"(a[0]), "r"(a[1]), "r"(a[2]), "r"(a[3]), "r"(b0), "r"(b1));
}
__device__ __forceinline__ void cp_async16(uint32_t dst, const void* src, int srcsz) {
    asm volatile("cp.async.cg.shared.global [%0], [%1], 16, %2;"
                 :: "r"(dst), "l"(src), "r"(srcsz) : "memory");
}
// 8 floats -> one 16B fp16 STS.128
__device__ __forceinline__ void st_f16x8(char* p, const float* v) {
    uint4 u;
    u.x = pk_f16x2(v[0], v[1]);
    u.y = pk_f16x2(v[2], v[3]);
    u.z = pk_f16x2(v[4], v[5]);
    u.w = pk_f16x2(v[6], v[7]);
    *(uint4*)p = u;
}

__global__ __launch_bounds__(THREADS, 3)
void meshconv_kernel(const float* __restrict__ x,
                     const void* __restrict__ nbr_raw,
                     const float* __restrict__ bias,
                     float* __restrict__ out, int E) {
    extern __shared__ char smem[];
    const uint32_t sbase = smem_u32(smem);
    const int tid  = threadIdx.x;
    const int lane = tid & 31;
    const int warp = tid >> 5;
    int* sIdx = (int*)(smem + SM_IDX);

    const int e0 = blockIdx.x * TILE_E;

    // ---- resolve neighbor indices once ----
    {
        const int er = (e0 + tid) < E ? (e0 + tid) : (E - 1);
        long long n[4];
        if (g_nbr64) {
            const long long* nb = (const long long*)nbr_raw + (size_t)er * 4;
            n[0] = nb[0]; n[1] = nb[1]; n[2] = nb[2]; n[3] = nb[3];
        } else {
            const int* nb = (const int*)nbr_raw + (size_t)er * 4;
            n[0] = nb[0]; n[1] = nb[1]; n[2] = nb[2]; n[3] = nb[3];
        }
        int4 w;
        w.x = (n[0] < 0) ? -1 : (n[0] >= E ? E - 1 : (int)n[0]);
        w.y = (n[1] < 0) ? -1 : (n[1] >= E ? E - 1 : (int)n[1]);
        w.z = (n[2] < 0) ? -1 : (n[2] >= E ? E - 1 : (int)n[2]);
        w.w = (n[3] < 0) ? -1 : (n[3] >= E ? E - 1 : (int)n[3]);
        *(int4*)(sIdx + tid * 4) = w;
    }
    __syncwarp();

    const int j8 = lane >> 3, c8 = lane & 7;     // gather roles
    const int el = lane & 7,  sl = lane >> 3;    // compute roles
    const uint32_t scr = sbase + SM_SCR + warp * SCR_W;
    char* scrp = smem + SM_SCR + warp * SCR_W;
    char* aW   = smem + SM_A;

    #pragma unroll
    for (int ch = 0; ch < 4; ch++) {
        // ---- cooperative full-line gather: 8 elements x 4 neighbor rows ----
        #pragma unroll
        for (int i = 0; i < 8; i++) {
            int eg  = warp * 32 + ch * 8 + i;
            int idx = sIdx[eg * 4 + j8];
            const float* src = x + (size_t)(idx < 0 ? 0 : idx) * 32 + c8 * 4;
            cp_async16(scr + i * EFOOT + j8 * 144 + c8 * 16, src, idx < 0 ? 0 : 16);
        }
        asm volatile("cp.async.commit_group;" ::: "memory");
        asm volatile("cp.async.wait_group 0;" ::: "memory");
        __syncwarp();

        // ---- local feature build: lane owns (element el, 8-channel slice sl) ----
        const int egl = warp * 32 + ch * 8 + el;
        const int erg = (e0 + egl) < E ? (e0 + egl) : (E - 1);

        float4 a0l = *(const float4*)(scrp + el * EFOOT + 0 * 144 + sl * 32);
        float4 a0h = *(const float4*)(scrp + el * EFOOT + 0 * 144 + sl * 32 + 16);
        float4 a1l = *(const float4*)(scrp + el * EFOOT + 1 * 144 + sl * 32);
        float4 a1h = *(const float4*)(scrp + el * EFOOT + 1 * 144 + sl * 32 + 16);
        float4 b0l = *(const float4*)(scrp + el * EFOOT + 2 * 144 + sl * 32);
        float4 b0h = *(const float4*)(scrp + el * EFOOT + 2 * 144 + sl * 32 + 16);
        float4 b1l = *(const float4*)(scrp + el * EFOOT + 3 * 144 + sl * 32);
        float4 b1h = *(const float4*)(scrp + el * EFOOT + 3 * 144 + sl * 32 + 16);
        float4 xv0 = __ldg((const float4*)(x + (size_t)erg * 32 + sl * 8));
        float4 xv1 = __ldg((const float4*)(x + (size_t)erg * 32 + sl * 8 + 4));

        float A0[8] = {a0l.x,a0l.y,a0l.z,a0l.w,a0h.x,a0h.y,a0h.z,a0h.w};
        float A1[8] = {a1l.x,a1l.y,a1l.z,a1l.w,a1h.x,a1h.y,a1h.z,a1h.w};
        float B0[8] = {b0l.x,b0l.y,b0l.z,b0l.w,b0h.x,b0h.y,b0h.z,b0h.w};
        float B1[8] = {b1l.x,b1l.y,b1l.z,b1l.w,b1h.x,b1h.y,b1h.z,b1h.w};
        float XV[8] = {xv0.x,xv0.y,xv0.z,xv0.w,xv1.x,xv1.y,xv1.z,xv1.w};

        float g1[8], g2[8], g3[8], g4[8];
        #pragma unroll
        for (int j = 0; j < 8; j++) {
            float sa = A0[j] + A1[j], sb = B0[j] + B1[j];
            float da = fabsf(A0[j] - A1[j]), db = fabsf(B0[j] - B1[j]);
            g1[j] = sa + sb;
            g2[j] = da + db;
            g3[j] = fabsf(sa - sb);
            g4[j] = fabsf(da - db);
        }

        char* arow = aW + egl * RSTRIDE + sl * 16;
        st_f16x8(arow + 0 * 64, XV);
        st_f16x8(arow + 1 * 64, g1);
        st_f16x8(arow + 2 * 64, g2);
        st_f16x8(arow + 3 * 64, g3);
        st_f16x8(arow + 4 * 64, g4);
        __syncwarp();
    }
    __syncwarp();

    // ---- MMA over own 32 rows: single term ----
    float acc[2][8][4];
    #pragma unroll
    for (int st = 0; st < 2; st++)
        #pragma unroll
        for (int nn = 0; nn < 8; nn++)
            #pragma unroll
            for (int q = 0; q < 4; q++) acc[st][nn][q] = 0.0f;

    const uint32_t arow = (uint32_t)(warp * 32 + (lane & 15));
    const uint32_t aoff = ((uint32_t)(lane >> 4)) * 16;
    const uint32_t a0 = sbase + SM_A + arow * RSTRIDE + aoff;
    const uint32_t a1 = a0 + 16 * RSTRIDE;

    #pragma unroll
    for (int ks = 0; ks < 10; ks++) {
        uint32_t f0[4], f1[4];
        ldsm_x4(f0, a0 + ks * 32);
        ldsm_x4(f1, a1 + ks * 32);
        #pragma unroll
        for (int nn = 0; nn < 8; nn++) {
            uint2 f = __ldg(&g_Wfrag[(ks * 8 + nn) * 32 + lane]);
            mma_f16(acc[0][nn], f0, f.x, f.y);
            mma_f16(acc[1][nn], f1, f.x, f.y);
        }
    }

    // ---- Epilogue ----
    const int colq = (lane & 3) * 2;
    #pragma unroll
    for (int nn = 0; nn < 8; nn++) {
        int col = nn * 8 + colq;
        float2 bv = *(const float2*)(bias + col);
        #pragma unroll
        for (int st = 0; st < 2; st++) {
            int rbase = e0 + warp * 32 + st * 16 + (lane >> 2);
            if (rbase < E) {
                float2 o0 = make_float2(acc[st][nn][0] + bv.x, acc[st][nn][1] + bv.y);
                *(float2*)(out + (size_t)rbase * 64 + col) = o0;
            }
            if (rbase + 8 < E) {
                float2 o1 = make_float2(acc[st][nn][2] + bv.x, acc[st][nn][3] + bv.y);
                *(float2*)(out + (size_t)(rbase + 8) * 64 + col) = o1;
            }
        }
    }
}

extern "C" void kernel_launch(void* const* d_in, const int* in_sizes, int n_in,
                              void* d_out, int out_size) {
    const int E = out_size / 64;
    const float* x = nullptr; const void* nbr = nullptr;
    const float* W = nullptr; const float* b = nullptr;

    for (int i = 0; i < n_in; i++) {
        long long sz = in_sizes[i];
        if (sz == (long long)E * 32)      x   = (const float*)d_in[i];
        else if (sz == (long long)E * 4)  nbr = d_in[i];
        else if (sz == 64 * NK)           W   = (const float*)d_in[i];
        else if (sz == 64)                b   = (const float*)d_in[i];
    }
    float* out = (float*)d_out;

    meshconv_prep<<<(WF_N + 255) / 256, 256>>>(W, nbr, E);

    cudaFuncSetAttribute(meshconv_kernel,
                         cudaFuncAttributeMaxDynamicSharedMemorySize, SM_TOTAL);
    int nb = (E + TILE_E - 1) / TILE_E;
    meshconv_kernel<<<nb, THREADS, SM_TOTAL>>>(x, nbr, b, out, E);
}

// round 15
// speedup vs baseline: 1.6276x; 1.0176x over previous
#include <cuda_runtime.h>
#include <cuda_fp16.h>
#include <cstdint>

// MeshConv via mma.sync m16n8k16 fp16 single-term (rel_err ~3e-4).
// 4-CTA/SM variant: chunks of 4 elements, 4-channel compute slices to cut
// register pressure; cp.async full-line gather; warp-independent tiles.

#define NK      160
#define TILE_E  128
#define THREADS 128
#define RSTRIDE 336                      // A row stride bytes (16*21, odd 16B units)
#define A_BYTES (TILE_E * RSTRIDE)       // 43008
#define EFOOT   672                      // scratch per element (== 32 mod 128)
#define SCR_W   (4 * EFOOT)              // 2688 per warp
#define SM_A    0
#define SM_SCR  A_BYTES                  // 43008
#define SM_IDX  (SM_SCR + 4 * SCR_W)     // 53760
#define SM_TOTAL (SM_IDX + TILE_E * 4 * 4)   // 55808
#define WF_N    (10 * 8 * 32)

__device__ uint2 g_Wfrag[WF_N];          // {b0, b1} fp16x2
__device__ int   g_nbr64;

__device__ __forceinline__ uint32_t pk_f16x2(float lo, float hi) {
    uint32_t r;
    asm("cvt.rn.f16x2.f32 %0, %1, %2;" : "=r"(r) : "f"(hi), "f"(lo));
    return r;
}

__global__ void meshconv_prep(const float* __restrict__ W,
                              const void* __restrict__ nbr_raw, int E) {
    int i = blockIdx.x * blockDim.x + threadIdx.x;
    if (i < WF_N) {
        int lane = i & 31;
        int n    = (i >> 5) & 7;
        int ks   = i >> 8;
        int ng = n * 8 + (lane >> 2);
        int k0 = ks * 16 + (lane & 3) * 2;
        uint2 f;
        f.x = pk_f16x2(W[ng * NK + k0],     W[ng * NK + k0 + 1]);
        f.y = pk_f16x2(W[ng * NK + k0 + 8], W[ng * NK + k0 + 9]);
        g_Wfrag[i] = f;
    }
    if (i == 0) {
        const long long* p = (const long long*)nbr_raw;
        int ok = 1;
        #pragma unroll
        for (int j = 0; j < 16; j++) {
            long long v = p[j];
            if (v < -(long long)E || v >= (long long)E) ok = 0;
        }
        g_nbr64 = ok;
    }
}

__device__ __forceinline__ uint32_t smem_u32(const void* p) {
    uint32_t a;
    asm("{ .reg .u64 t; cvta.to.shared.u64 t, %1; cvt.u32.u64 %0, t; }" : "=r"(a) : "l"(p));
    return a;
}
__device__ __forceinline__ void ldsm_x4(uint32_t* r, uint32_t addr) {
    asm volatile("ldmatrix.sync.aligned.m8n8.x4.shared.b16 {%0,%1,%2,%3}, [%4];"
                 : "=r"(r[0]), "=r"(r[1]), "=r"(r[2]), "=r"(r[3]) : "r"(addr));
}
__device__ __forceinline__ void mma_f16(float* d, const uint32_t* a,
                                        uint32_t b0, uint32_t b1) {
    asm volatile(
        "mma.sync.aligned.m16n8k16.row.col.f32.f16.f16.f32 "
        "{%0,%1,%2,%3}, {%4,%5,%6,%7}, {%8,%9}, {%0,%1,%2,%3};"
        : "+f"(d[0]), "+f"(d[1]), "+f"(d[2]), "+f"(d[3])
        : "r"(a[0]), "r"(a[1]), "r"(a[2]), "r"(a[3]), "r"(b0), "r"(b1));
}
__device__ __forceinline__ void cp_async16(uint32_t dst, const void* src, int srcsz) {
    asm volatile("cp.async.cg.shared.global [%0], [%1], 16, %2;"
                 :: "r"(dst), "l"(src), "r"(srcsz) : "memory");
}

__global__ __launch_bounds__(THREADS, 4)
void meshconv_kernel(const float* __restrict__ x,
                     const void* __restrict__ nbr_raw,
                     const float* __restrict__ bias,
                     float* __restrict__ out, int E) {
    extern __shared__ char smem[];
    const uint32_t sbase = smem_u32(smem);
    const int tid  = threadIdx.x;
    const int lane = tid & 31;
    const int warp = tid >> 5;
    int* sIdx = (int*)(smem + SM_IDX);

    const int e0 = blockIdx.x * TILE_E;

    // ---- resolve neighbor indices once ----
    {
        const int er = (e0 + tid) < E ? (e0 + tid) : (E - 1);
        long long n[4];
        if (g_nbr64) {
            const long long* nb = (const long long*)nbr_raw + (size_t)er * 4;
            n[0] = nb[0]; n[1] = nb[1]; n[2] = nb[2]; n[3] = nb[3];
        } else {
            const int* nb = (const int*)nbr_raw + (size_t)er * 4;
            n[0] = nb[0]; n[1] = nb[1]; n[2] = nb[2]; n[3] = nb[3];
        }
        int4 w;
        w.x = (n[0] < 0) ? -1 : (n[0] >= E ? E - 1 : (int)n[0]);
        w.y = (n[1] < 0) ? -1 : (n[1] >= E ? E - 1 : (int)n[1]);
        w.z = (n[2] < 0) ? -1 : (n[2] >= E ? E - 1 : (int)n[2]);
        w.w = (n[3] < 0) ? -1 : (n[3] >= E ? E - 1 : (int)n[3]);
        *(int4*)(sIdx + tid * 4) = w;
    }
    __syncwarp();

    const int j8 = lane >> 3, c8 = lane & 7;     // gather roles (4 nbr x 8 chunks16B)
    const int el = lane & 3,  sl = lane >> 2;    // compute roles (4 el x 8 slices of 4ch)
    const uint32_t scr = sbase + SM_SCR + warp * SCR_W;
    char* scrp = smem + SM_SCR + warp * SCR_W;
    char* aW   = smem + SM_A;

    #pragma unroll
    for (int ch = 0; ch < 8; ch++) {
        // ---- cooperative full-line gather: 4 elements x 4 neighbor rows ----
        #pragma unroll
        for (int i = 0; i < 4; i++) {
            int eg  = warp * 32 + ch * 4 + i;
            int idx = sIdx[eg * 4 + j8];
            const float* src = x + (size_t)(idx < 0 ? 0 : idx) * 32 + c8 * 4;
            cp_async16(scr + i * EFOOT + j8 * 144 + c8 * 16, src, idx < 0 ? 0 : 16);
        }
        asm volatile("cp.async.commit_group;" ::: "memory");
        asm volatile("cp.async.wait_group 0;" ::: "memory");
        __syncwarp();

        // ---- local feature build: lane owns (element el, 4-channel slice sl) ----
        const int egl = warp * 32 + ch * 4 + el;
        const int erg = (e0 + egl) < E ? (e0 + egl) : (E - 1);

        float4 A0 = *(const float4*)(scrp + el * EFOOT + 0 * 144 + sl * 16);
        float4 A1 = *(const float4*)(scrp + el * EFOOT + 1 * 144 + sl * 16);
        float4 B0 = *(const float4*)(scrp + el * EFOOT + 2 * 144 + sl * 16);
        float4 B1 = *(const float4*)(scrp + el * EFOOT + 3 * 144 + sl * 16);
        float4 XV = __ldg((const float4*)(x + (size_t)erg * 32 + sl * 4));

        float a0[4] = {A0.x, A0.y, A0.z, A0.w};
        float a1[4] = {A1.x, A1.y, A1.z, A1.w};
        float b0[4] = {B0.x, B0.y, B0.z, B0.w};
        float b1[4] = {B1.x, B1.y, B1.z, B1.w};
        float g1[4], g2[4], g3[4], g4[4];
        #pragma unroll
        for (int j = 0; j < 4; j++) {
            float sa = a0[j] + a1[j], sb = b0[j] + b1[j];
            float da = fabsf(a0[j] - a1[j]), db = fabsf(b0[j] - b1[j]);
            g1[j] = sa + sb;
            g2[j] = da + db;
            g3[j] = fabsf(sa - sb);
            g4[j] = fabsf(da - db);
        }

        // slice sl of group g at byte offset g*64 + sl*8 (uint2 STS each)
        char* arow = aW + egl * RSTRIDE + sl * 8;
        *(uint2*)(arow + 0 * 64) = make_uint2(pk_f16x2(XV.x, XV.y), pk_f16x2(XV.z, XV.w));
        *(uint2*)(arow + 1 * 64) = make_uint2(pk_f16x2(g1[0], g1[1]), pk_f16x2(g1[2], g1[3]));
        *(uint2*)(arow + 2 * 64) = make_uint2(pk_f16x2(g2[0], g2[1]), pk_f16x2(g2[2], g2[3]));
        *(uint2*)(arow + 3 * 64) = make_uint2(pk_f16x2(g3[0], g3[1]), pk_f16x2(g3[2], g3[3]));
        *(uint2*)(arow + 4 * 64) = make_uint2(pk_f16x2(g4[0], g4[1]), pk_f16x2(g4[2], g4[3]));
        __syncwarp();   // scratch reuse next chunk
    }
    __syncwarp();

    // ---- MMA over own 32 rows: single term ----
    float acc[2][8][4];
    #pragma unroll
    for (int st = 0; st < 2; st++)
        #pragma unroll
        for (int nn = 0; nn < 8; nn++)
            #pragma unroll
            for (int q = 0; q < 4; q++) acc[st][nn][q] = 0.0f;

    const uint32_t arow = (uint32_t)(warp * 32 + (lane & 15));
    const uint32_t aoff = ((uint32_t)(lane >> 4)) * 16;
    const uint32_t a0p = sbase + SM_A + arow * RSTRIDE + aoff;
    const uint32_t a1p = a0p + 16 * RSTRIDE;

    #pragma unroll
    for (int ks = 0; ks < 10; ks++) {
        uint32_t f0[4], f1[4];
        ldsm_x4(f0, a0p + ks * 32);
        ldsm_x4(f1, a1p + ks * 32);
        #pragma unroll
        for (int nn = 0; nn < 8; nn++) {
            uint2 f = __ldg(&g_Wfrag[(ks * 8 + nn) * 32 + lane]);
            mma_f16(acc[0][nn], f0, f.x, f.y);
            mma_f16(acc[1][nn], f1, f.x, f.y);
        }
    }

    // ---- Epilogue ----
    const int colq = (lane & 3) * 2;
    #pragma unroll
    for (int nn = 0; nn < 8; nn++) {
        int col = nn * 8 + colq;
        float2 bv = *(const float2*)(bias + col);
        #pragma unroll
        for (int st = 0; st < 2; st++) {
            int rbase = e0 + warp * 32 + st * 16 + (lane >> 2);
            if (rbase < E) {
                float2 o0 = make_float2(acc[st][nn][0] + bv.x, acc[st][nn][1] + bv.y);
                *(float2*)(out + (size_t)rbase * 64 + col) = o0;
            }
            if (rbase + 8 < E) {
                float2 o1 = make_float2(acc[st][nn][2] + bv.x, acc[st][nn][3] + bv.y);
                *(float2*)(out + (size_t)(rbase + 8) * 64 + col) = o1;
            }
        }
    }
}

extern "C" void kernel_launch(void* const* d_in, const int* in_sizes, int n_in,
                              void* d_out, int out_size) {
    const int E = out_size / 64;
    const float* x = nullptr; const void* nbr = nullptr;
    const float* W = nullptr; const float* b = nullptr;

    for (int i = 0; i < n_in; i++) {
        long long sz = in_sizes[i];
        if (sz == (long long)E * 32)      x   = (const float*)d_in[i];
        else if (sz == (long long)E * 4)  nbr = d_in[i];
        else if (sz == 64 * NK)           W   = (const float*)d_in[i];
        else if (sz == 64)                b   = (const float*)d_in[i];
    }
    float* out = (float*)d_out;

    meshconv_prep<<<(WF_N + 255) / 256, 256>>>(W, nbr, E);

    cudaFuncSetAttribute(meshconv_kernel,
                         cudaFuncAttributeMaxDynamicSharedMemorySize, SM_TOTAL);
    int nb = (E + TILE_E - 1) / TILE_E;
    meshconv_kernel<<<nb, THREADS, SM_TOTAL>>>(x, nbr, b, out, E);
}

// round 16
// speedup vs baseline: 1.7299x; 1.0628x over previous
#include <cuda_runtime.h>
#include <cuda_fp16.h>
#include <cstdint>

// MeshConv via mma.sync m16n8k16 fp16 single-term (rel_err ~3e-4).
// Direct-LDG full-line gather straight into compute lanes' registers
// (no scratch round-trip). Warp-independent tiles, 4 CTAs/SM.

#define NK      160
#define TILE_E  128
#define THREADS 128
#define RSTRIDE 336                      // A row stride bytes
#define A_BYTES (TILE_E * RSTRIDE)       // 43008
#define SM_A    0
#define SM_IDX  A_BYTES                  // 43008
#define SM_TOTAL (SM_IDX + TILE_E * 4 * 4)   // 45056
#define WF_N    (10 * 8 * 32)

__device__ uint2 g_Wfrag[WF_N];          // {b0, b1} fp16x2
__device__ int   g_nbr64;

__device__ __forceinline__ uint32_t pk_f16x2(float lo, float hi) {
    uint32_t r;
    asm("cvt.rn.f16x2.f32 %0, %1, %2;" : "=r"(r) : "f"(hi), "f"(lo));
    return r;
}

__global__ void meshconv_prep(const float* __restrict__ W,
                              const void* __restrict__ nbr_raw, int E) {
    int i = blockIdx.x * blockDim.x + threadIdx.x;
    if (i < WF_N) {
        int lane = i & 31;
        int n    = (i >> 5) & 7;
        int ks   = i >> 8;
        int ng = n * 8 + (lane >> 2);
        int k0 = ks * 16 + (lane & 3) * 2;
        uint2 f;
        f.x = pk_f16x2(W[ng * NK + k0],     W[ng * NK + k0 + 1]);
        f.y = pk_f16x2(W[ng * NK + k0 + 8], W[ng * NK + k0 + 9]);
        g_Wfrag[i] = f;
    }
    if (i == 0) {
        const long long* p = (const long long*)nbr_raw;
        int ok = 1;
        #pragma unroll
        for (int j = 0; j < 16; j++) {
            long long v = p[j];
            if (v < -(long long)E || v >= (long long)E) ok = 0;
        }
        g_nbr64 = ok;
    }
}

__device__ __forceinline__ uint32_t smem_u32(const void* p) {
    uint32_t a;
    asm("{ .reg .u64 t; cvta.to.shared.u64 t, %1; cvt.u32.u64 %0, t; }" : "=r"(a) : "l"(p));
    return a;
}
__device__ __forceinline__ void ldsm_x4(uint32_t* r, uint32_t addr) {
    asm volatile("ldmatrix.sync.aligned.m8n8.x4.shared.b16 {%0,%1,%2,%3}, [%4];"
                 : "=r"(r[0]), "=r"(r[1]), "=r"(r[2]), "=r"(r[3]) : "r"(addr));
}
__device__ __forceinline__ void mma_f16(float* d, const uint32_t* a,
                                        uint32_t b0, uint32_t b1) {
    asm volatile(
        "mma.sync.aligned.m16n8k16.row.col.f32.f16.f16.f32 "
        "{%0,%1,%2,%3}, {%4,%5,%6,%7}, {%8,%9}, {%0,%1,%2,%3};"
        : "+f"(d[0]), "+f"(d[1]), "+f"(d[2]), "+f"(d[3])
        : "r"(a[0]), "r"(a[1]), "r"(a[2]), "r"(a[3]), "r"(b0), "r"(b1));
}

__global__ __launch_bounds__(THREADS, 4)
void meshconv_kernel(const float* __restrict__ x,
                     const void* __restrict__ nbr_raw,
                     const float* __restrict__ bias,
                     float* __restrict__ out, int E) {
    extern __shared__ char smem[];
    const uint32_t sbase = smem_u32(smem);
    const int tid  = threadIdx.x;
    const int lane = tid & 31;
    const int warp = tid >> 5;
    int* sIdx = (int*)(smem + SM_IDX);

    const int e0 = blockIdx.x * TILE_E;

    // ---- resolve neighbor indices once ----
    {
        const int er = (e0 + tid) < E ? (e0 + tid) : (E - 1);
        long long n[4];
        if (g_nbr64) {
            const long long* nb = (const long long*)nbr_raw + (size_t)er * 4;
            n[0] = nb[0]; n[1] = nb[1]; n[2] = nb[2]; n[3] = nb[3];
        } else {
            const int* nb = (const int*)nbr_raw + (size_t)er * 4;
            n[0] = nb[0]; n[1] = nb[1]; n[2] = nb[2]; n[3] = nb[3];
        }
        int4 w;
        w.x = (n[0] < 0) ? -1 : (n[0] >= E ? E - 1 : (int)n[0]);
        w.y = (n[1] < 0) ? -1 : (n[1] >= E ? E - 1 : (int)n[1]);
        w.z = (n[2] < 0) ? -1 : (n[2] >= E ? E - 1 : (int)n[2]);
        w.w = (n[3] < 0) ? -1 : (n[3] >= E ? E - 1 : (int)n[3]);
        *(int4*)(sIdx + tid * 4) = w;
    }
    __syncwarp();

    // compute roles: el = lane>>3 (element within chunk), sl = lane&7 (16B slice)
    const int el = lane >> 3, sl = lane & 7;
    char* aW = smem + SM_A;

    #pragma unroll
    for (int ch = 0; ch < 8; ch++) {
        const int egl = warp * 32 + ch * 4 + el;
        const int erg = (e0 + egl) < E ? (e0 + egl) : (E - 1);

        // neighbor indices for this element (LDS broadcast across the 8 lanes)
        int4 nb = *(const int4*)(sIdx + egl * 4);
        float m0 = nb.x >= 0 ? 1.0f : 0.0f;  int r0 = nb.x >= 0 ? nb.x : 0;
        float m1 = nb.y >= 0 ? 1.0f : 0.0f;  int r1 = nb.y >= 0 ? nb.y : 0;
        float m2 = nb.z >= 0 ? 1.0f : 0.0f;  int r2 = nb.z >= 0 ? nb.z : 0;
        float m3 = nb.w >= 0 ? 1.0f : 0.0f;  int r3 = nb.w >= 0 ? nb.w : 0;

        // direct full-line gather: each instruction covers 4 rows x 128B,
        // 8 consecutive lanes per line -> fully coalesced, data in registers.
        float4 A0 = __ldg((const float4*)(x + (size_t)r0 * 32 + sl * 4));
        float4 A1 = __ldg((const float4*)(x + (size_t)r1 * 32 + sl * 4));
        float4 B0 = __ldg((const float4*)(x + (size_t)r2 * 32 + sl * 4));
        float4 B1 = __ldg((const float4*)(x + (size_t)r3 * 32 + sl * 4));
        float4 XV = __ldg((const float4*)(x + (size_t)erg * 32 + sl * 4));

        float a0[4] = {A0.x * m0, A0.y * m0, A0.z * m0, A0.w * m0};
        float a1[4] = {A1.x * m1, A1.y * m1, A1.z * m1, A1.w * m1};
        float b0[4] = {B0.x * m2, B0.y * m2, B0.z * m2, B0.w * m2};
        float b1[4] = {B1.x * m3, B1.y * m3, B1.z * m3, B1.w * m3};

        float g1[4], g2[4], g3[4], g4[4];
        #pragma unroll
        for (int j = 0; j < 4; j++) {
            float sa = a0[j] + a1[j], sb = b0[j] + b1[j];
            float da = fabsf(a0[j] - a1[j]), db = fabsf(b0[j] - b1[j]);
            g1[j] = sa + sb;
            g2[j] = da + db;
            g3[j] = fabsf(sa - sb);
            g4[j] = fabsf(da - db);
        }

        // slice sl of group g at byte offset g*64 + sl*8 (uint2 STS each)
        char* arow = aW + egl * RSTRIDE + sl * 8;
        *(uint2*)(arow + 0 * 64) = make_uint2(pk_f16x2(XV.x, XV.y), pk_f16x2(XV.z, XV.w));
        *(uint2*)(arow + 1 * 64) = make_uint2(pk_f16x2(g1[0], g1[1]), pk_f16x2(g1[2], g1[3]));
        *(uint2*)(arow + 2 * 64) = make_uint2(pk_f16x2(g2[0], g2[1]), pk_f16x2(g2[2], g2[3]));
        *(uint2*)(arow + 3 * 64) = make_uint2(pk_f16x2(g3[0], g3[1]), pk_f16x2(g3[2], g3[3]));
        *(uint2*)(arow + 4 * 64) = make_uint2(pk_f16x2(g4[0], g4[1]), pk_f16x2(g4[2], g4[3]));
    }
    __syncwarp();   // STS visible to ldsm

    // ---- MMA over own 32 rows: single term ----
    float acc[2][8][4];
    #pragma unroll
    for (int st = 0; st < 2; st++)
        #pragma unroll
        for (int nn = 0; nn < 8; nn++)
            #pragma unroll
            for (int q = 0; q < 4; q++) acc[st][nn][q] = 0.0f;

    const uint32_t arow = (uint32_t)(warp * 32 + (lane & 15));
    const uint32_t aoff = ((uint32_t)(lane >> 4)) * 16;
    const uint32_t a0p = sbase + SM_A + arow * RSTRIDE + aoff;
    const uint32_t a1p = a0p + 16 * RSTRIDE;

    #pragma unroll
    for (int ks = 0; ks < 10; ks++) {
        uint32_t f0[4], f1[4];
        ldsm_x4(f0, a0p + ks * 32);
        ldsm_x4(f1, a1p + ks * 32);
        #pragma unroll
        for (int nn = 0; nn < 8; nn++) {
            uint2 f = __ldg(&g_Wfrag[(ks * 8 + nn) * 32 + lane]);
            mma_f16(acc[0][nn], f0, f.x, f.y);
            mma_f16(acc[1][nn], f1, f.x, f.y);
        }
    }

    // ---- Epilogue ----
    const int colq = (lane & 3) * 2;
    #pragma unroll
    for (int nn = 0; nn < 8; nn++) {
        int col = nn * 8 + colq;
        float2 bv = *(const float2*)(bias + col);
        #pragma unroll
        for (int st = 0; st < 2; st++) {
            int rbase = e0 + warp * 32 + st * 16 + (lane >> 2);
            if (rbase < E) {
                float2 o0 = make_float2(acc[st][nn][0] + bv.x, acc[st][nn][1] + bv.y);
                *(float2*)(out + (size_t)rbase * 64 + col) = o0;
            }
            if (rbase + 8 < E) {
                float2 o1 = make_float2(acc[st][nn][2] + bv.x, acc[st][nn][3] + bv.y);
                *(float2*)(out + (size_t)(rbase + 8) * 64 + col) = o1;
            }
        }
    }
}

extern "C" void kernel_launch(void* const* d_in, const int* in_sizes, int n_in,
                              void* d_out, int out_size) {
    const int E = out_size / 64;
    const float* x = nullptr; const void* nbr = nullptr;
    const float* W = nullptr; const float* b = nullptr;

    for (int i = 0; i < n_in; i++) {
        long long sz = in_sizes[i];
        if (sz == (long long)E * 32)      x   = (const float*)d_in[i];
        else if (sz == (long long)E * 4)  nbr = d_in[i];
        else if (sz == 64 * NK)           W   = (const float*)d_in[i];
        else if (sz == 64)                b   = (const float*)d_in[i];
    }
    float* out = (float*)d_out;

    meshconv_prep<<<(WF_N + 255) / 256, 256>>>(W, nbr, E);

    cudaFuncSetAttribute(meshconv_kernel,
                         cudaFuncAttributeMaxDynamicSharedMemorySize, SM_TOTAL);
    int nb = (E + TILE_E - 1) / TILE_E;
    meshconv_kernel<<<nb, THREADS, SM_TOTAL>>>(x, nbr, b, out, E);
}